// round 6
// baseline (speedup 1.0000x reference)
#include <cuda_runtime.h>
#include <math.h>

#define NB   32
#define RESO 256
#define KK   1024
#define EPSF 1e-6f

// log2(e) and its square, ln(2)
#define LOG2E   1.4426950408889634f
#define LOG2E2  2.0813689810056077f
#define LN2     0.6931471805599453f

// Scratch (no allocations allowed).
// src: (sx, sy, |s|^2 * log2e^2, 0)
// trg: (tx', ty', |t'|^2, 0) with t' = t - eps
__device__ float4 g_src4[NB * KK];
__device__ float4 g_trg4[NB * KK];
__device__ double g_loss;
__device__ double g_vis;
__device__ unsigned int g_done;

__device__ __forceinline__ float sqrt_approx(float x) {
    float r; asm("sqrt.approx.f32 %0, %1;" : "=f"(r) : "f"(x)); return r;
}
__device__ __forceinline__ float ex2_approx(float x) {
    float r; asm("ex2.approx.f32 %0, %1;" : "=f"(r) : "f"(x)); return r;
}
__device__ __forceinline__ float lg2_approx(float x) {
    float r; asm("lg2.approx.f32 %0, %1;" : "=f"(r) : "f"(x)); return r;
}

// ---------------------------------------------------------------------------
// Kernel 1: bilinear sampling; emits packed float4 per point.
// ---------------------------------------------------------------------------
__global__ void sample_kernel(const float* __restrict__ src_flow,
                              const float* __restrict__ trg_flow,
                              const float* __restrict__ src_kp,
                              const float* __restrict__ trg_kp) {
    int tid = blockIdx.x * blockDim.x + threadIdx.x;
    if (tid == 0) { g_loss = 0.0; g_vis = 0.0; g_done = 0u; }
    if (tid >= 2 * NB * KK) return;

    int sel = tid >= NB * KK;          // 0 = src, 1 = trg
    int idx = sel ? (tid - NB * KK) : tid;
    const float* flow = sel ? trg_flow : src_flow;
    const float2 p = reinterpret_cast<const float2*>(sel ? trg_kp : src_kp)[idx];

    int   n = idx / KK;

    float x0f = floorf(p.x), y0f = floorf(p.y);
    int   x0  = (int)x0f,    y0  = (int)y0f;
    float wx  = p.x - x0f,   wy  = p.y - y0f;
    int   x1  = x0 + 1,      y1  = y0 + 1;

    int x0c = min(max(x0, 0), RESO - 1);
    int x1c = min(max(x1, 0), RESO - 1);
    int y0c = min(max(y0, 0), RESO - 1);
    int y1c = min(max(y1, 0), RESO - 1);

    float vx0 = (x0 >= 0 && x0 < RESO) ? 1.f : 0.f;
    float vx1 = (x1 >= 0 && x1 < RESO) ? 1.f : 0.f;
    float vy0 = (y0 >= 0 && y0 < RESO) ? 1.f : 0.f;
    float vy1 = (y1 >= 0 && y1 < RESO) ? 1.f : 0.f;

    const float2* base = reinterpret_cast<const float2*>(flow) + (size_t)n * RESO * RESO;

    float2 v00 = base[y0c * RESO + x0c];
    float2 v10 = base[y0c * RESO + x1c];
    float2 v01 = base[y1c * RESO + x0c];
    float2 v11 = base[y1c * RESO + x1c];

    float w00 = (1.f - wx) * (1.f - wy) * vx0 * vy0;
    float w10 = wx * (1.f - wy) * vx1 * vy0;
    float w01 = (1.f - wx) * wy * vx0 * vy1;
    float w11 = wx * wy * vx1 * vy1;

    float cx = v00.x * w00 + v10.x * w10 + v01.x * w01 + v11.x * w11;
    float cy = v00.y * w00 + v10.y * w10 + v01.y * w01 + v11.y * w11;

    if (sel) {
        float txe = cx - EPSF, tye = cy - EPSF;
        g_trg4[idx] = make_float4(txe, tye, txe * txe + tye * tye, 0.f);
    } else {
        // pre-scale |s|^2 by log2e^2 so K2's q is in (log2e*dist)^2 units
        g_src4[idx] = make_float4(cx, cy, (cx * cx + cy * cy) * LOG2E2, 0.f);
    }
}

// ---------------------------------------------------------------------------
// Kernel 2 (fused): per (n, j):
//   acc = sum_i exp2(-sqrt( log2e^2 * dist(s_i, t'_j)^2 ))  [= sum exp(-dist)]
//   ce  = ln(acc) + dist_jj ; contrib = 2*ce*vis*wt
// grid = (K/64, N) = 512 blocks, block = 64. All 1024 i in smem (16 KB).
// MUFU-bound: per pair = 2 MUFU (SQRT, EX2-with-folded-neg) + 4 fma-pipe ops.
// Block-reduce + atomics; last finishing block writes out[0].
// ---------------------------------------------------------------------------
__global__ void __launch_bounds__(64) loss_kernel(const int* __restrict__ kp_vis,
                                                  const float* __restrict__ kp_wt,
                                                  float* __restrict__ out) {
    __shared__ float4 s_src[KK];
    const int n = blockIdx.y;
    const int j = blockIdx.x * 64 + threadIdx.x;

    // issue these early; consumed after the big loop
    const int   vis = (kp_vis[n * KK + j] != 0);
    const float wt  = kp_wt[n * KK + j];
    const float4 t  = g_trg4[n * KK + j];

    const float4* srcn = g_src4 + n * KK;
    #pragma unroll
    for (int i = threadIdx.x; i < KK; i += 64) s_src[i] = srcn[i];
    __syncthreads();

    // q' = log2e^2 * (|s|^2 - 2 s.t' + |t'|^2) = s.zC2 + a*sx + b*sy + ttC2
    const float a    = -2.0f * t.x * LOG2E2;
    const float b    = -2.0f * t.y * LOG2E2;
    const float ttC2 = t.z * LOG2E2;

    float acc0 = 0.f, acc1 = 0.f, acc2 = 0.f, acc3 = 0.f;
    #pragma unroll 2
    for (int i = 0; i < KK; i += 4) {
        float4 s0 = s_src[i + 0];
        float4 s1 = s_src[i + 1];
        float4 s2 = s_src[i + 2];
        float4 s3 = s_src[i + 3];

        float q0 = fmaf(s0.x, a, fmaf(s0.y, b, s0.z + ttC2));
        float q1 = fmaf(s1.x, a, fmaf(s1.y, b, s1.z + ttC2));
        float q2 = fmaf(s2.x, a, fmaf(s2.y, b, s2.z + ttC2));
        float q3 = fmaf(s3.x, a, fmaf(s3.y, b, s3.z + ttC2));

        float d0 = sqrt_approx(q0);   // = log2e * dist
        float d1 = sqrt_approx(q1);
        float d2 = sqrt_approx(q2);
        float d3 = sqrt_approx(q3);

        acc0 += ex2_approx(-d0);      // neg folds into MUFU operand
        acc1 += ex2_approx(-d1);
        acc2 += ex2_approx(-d2);
        acc3 += ex2_approx(-d3);
    }
    float acc = (acc0 + acc1) + (acc2 + acc3);

    // diagonal distance (plain units)
    float4 sj = s_src[j];
    float dx = sj.x - t.x, dy = sj.y - t.y;
    float djj = sqrt_approx(fmaf(dy, dy, dx * dx));

    float ce = lg2_approx(acc) * LN2 + djj;

    float contrib = vis ? 2.0f * ce * wt : 0.0f;
    float viscnt  = vis ? 1.0f : 0.0f;

    #pragma unroll
    for (int o = 16; o > 0; o >>= 1) {
        contrib += __shfl_down_sync(0xffffffffu, contrib, o);
        viscnt  += __shfl_down_sync(0xffffffffu, viscnt,  o);
    }
    __shared__ float s_v[2], s_c[2];
    if ((threadIdx.x & 31) == 0) {
        s_v[threadIdx.x >> 5] = contrib;
        s_c[threadIdx.x >> 5] = viscnt;
    }
    __syncthreads();
    if (threadIdx.x == 0) {
        atomicAdd(&g_loss, (double)(s_v[0] + s_v[1]));
        atomicAdd(&g_vis,  (double)(s_c[0] + s_c[1]));
        __threadfence();
        unsigned int done = atomicAdd(&g_done, 1u);
        if (done == gridDim.x * gridDim.y - 1) {
            double L = atomicAdd(&g_loss, 0.0);
            double V = atomicAdd(&g_vis, 0.0);
            out[0] = (float)(L / V);
        }
    }
}

extern "C" void kernel_launch(void* const* d_in, const int* in_sizes, int n_in,
                              void* d_out, int out_size) {
    const float* src_flow = (const float*)d_in[0];
    const float* trg_flow = (const float*)d_in[1];
    const float* src_kp   = (const float*)d_in[2];
    const float* trg_kp   = (const float*)d_in[3];
    const int*   kp_vis   = (const int*)d_in[4];
    const float* kp_wt    = (const float*)d_in[5];
    float* out = (float*)d_out;

    sample_kernel<<<(2 * NB * KK + 255) / 256, 256>>>(src_flow, trg_flow, src_kp, trg_kp);

    dim3 grid(KK / 64, NB);
    loss_kernel<<<grid, 64>>>(kp_vis, kp_wt, out);
}